// round 15
// baseline (speedup 1.0000x reference)
#include <cuda_runtime.h>
#include <cuda_bf16.h>
#include <cstdint>
#include <math.h>

#define B_  32
#define N_  64
#define D_  30
#define ND_ 64
#define H3_ 32
#define L_  8

// ---------------- device scratch ----------------
__device__ float g_xenc[B_*N_*H3_];
__device__ float g_x2[B_*N_];
__device__ float g_denc[D_*ND_*H3_];
__device__ float g_dsamp[D_*ND_*H3_];
__device__ float g_y2[D_*ND_];
__device__ float g_klpart[D_];
__device__ float4 g_vwd[D_*N_*ND_];          // [d][i=n*64+m] -> (s,t0,t1,t2)
__device__ float4 g_part[L_*B_*D_];

__constant__ float c_lamda[8] = {0.01f,0.1f,0.5f,1.0f,3.0f,5.0f,10.0f,20.0f};

// ---------------- JAX threefry2x32 (partitionable) ------------------
__device__ __forceinline__ uint32_t rotl32(uint32_t x, int r){
    return (x << r) | (x >> (32 - r));
}
__device__ float jax_uniform_1920(int i){
    uint32_t x0 = 0u;
    uint32_t x1 = (uint32_t)i;
    const uint32_t k0 = 0u, k1 = 42u;
    const uint32_t k2 = 0u ^ 42u ^ 0x1BD11BDAu;
    x0 += k0; x1 += k1;
    #define FOUR_ROUNDS(a,b,c,d) \
        x0 += x1; x1 = rotl32(x1,a); x1 ^= x0; \
        x0 += x1; x1 = rotl32(x1,b); x1 ^= x0; \
        x0 += x1; x1 = rotl32(x1,c); x1 ^= x0; \
        x0 += x1; x1 = rotl32(x1,d); x1 ^= x0;
    FOUR_ROUNDS(13,15,26,6);  x0 += k1; x1 += k2 + 1u;
    FOUR_ROUNDS(17,29,16,24); x0 += k2; x1 += k0 + 2u;
    FOUR_ROUNDS(13,15,26,6);  x0 += k0; x1 += k1 + 3u;
    FOUR_ROUNDS(17,29,16,24); x0 += k1; x1 += k2 + 4u;
    FOUR_ROUNDS(13,15,26,6);  x0 += k2; x1 += k0 + 5u;
    #undef FOUR_ROUNDS
    uint32_t bits = x0 ^ x1;
    uint32_t fb = (bits >> 9) | 0x3f800000u;
    return __uint_as_float(fb) - 1.0f;
}

// ---------------- GCN (both branches in one launch) ----------------------
__global__ void gcn_kernel(
    const float* __restrict__ xg0, const float* __restrict__ adjg0,
    const float* __restrict__ eW1, const float* __restrict__ eb1,
    const float* __restrict__ eW2, const float* __restrict__ eb2,
    const float* __restrict__ eW3, const float* __restrict__ eb3,
    const float* __restrict__ xg1, const float* __restrict__ adjg1,
    const float* __restrict__ dW1, const float* __restrict__ db1,
    const float* __restrict__ dW2, const float* __restrict__ db2,
    const float* __restrict__ dW3, const float* __restrict__ db3)
{
    extern __shared__ float sm[];
    float* adj_s = sm;             // 4096
    float* x_s   = sm + 4096;      // 4096
    float* t     = sm + 8192;      // 8192
    float* h     = sm + 16384;     // 8192
    int branch = (blockIdx.x >= 32) ? 1 : 0;
    int g = branch ? (blockIdx.x - 32) : blockIdx.x;
    const float* x   = (branch ? xg1   : xg0)   + g*64*64;
    const float* adj = (branch ? adjg1 : adjg0) + g*64*64;
    const float* W1 = branch ? dW1 : eW1; const float* b1 = branch ? db1 : eb1;
    const float* W2 = branch ? dW2 : eW2; const float* b2 = branch ? db2 : eb2;
    const float* W3 = branch ? dW3 : eW3; const float* b3 = branch ? db3 : eb3;
    int tid = threadIdx.x;

    for (int i = tid; i < 4096; i += 256){ adj_s[i] = adj[i]; x_s[i] = x[i]; }
    __syncthreads();

    for (int idx = tid; idx < 16*128; idx += 256){
        int rg = idx >> 7, j = idx & 127;
        const float* xr = x_s + rg*4*64;
        float a0=0.f,a1=0.f,a2=0.f,a3=0.f;
        #pragma unroll 8
        for (int k = 0; k < 64; k++){
            float w = W1[k*128+j];
            a0 += xr[k]*w; a1 += xr[64+k]*w; a2 += xr[128+k]*w; a3 += xr[192+k]*w;
        }
        t[(rg*4+0)*128+j]=a0; t[(rg*4+1)*128+j]=a1; t[(rg*4+2)*128+j]=a2; t[(rg*4+3)*128+j]=a3;
    }
    __syncthreads();
    for (int idx = tid; idx < 16*128; idx += 256){
        int rg = idx >> 7, j = idx & 127;
        const float* ar = adj_s + rg*4*64;
        float bb = b1[j];
        float a0=bb,a1=bb,a2=bb,a3=bb;
        #pragma unroll 8
        for (int k = 0; k < 64; k++){
            float w = t[k*128+j];
            a0 += ar[k]*w; a1 += ar[64+k]*w; a2 += ar[128+k]*w; a3 += ar[192+k]*w;
        }
        h[(rg*4+0)*128+j]=fmaxf(a0,0.f); h[(rg*4+1)*128+j]=fmaxf(a1,0.f);
        h[(rg*4+2)*128+j]=fmaxf(a2,0.f); h[(rg*4+3)*128+j]=fmaxf(a3,0.f);
    }
    __syncthreads();
    for (int idx = tid; idx < 16*64; idx += 256){
        int rg = idx >> 6, j = idx & 63;
        const float* hr = h + rg*4*128;
        float a0=0.f,a1=0.f,a2=0.f,a3=0.f;
        #pragma unroll 8
        for (int k = 0; k < 128; k++){
            float w = W2[k*64+j];
            a0 += hr[k]*w; a1 += hr[128+k]*w; a2 += hr[256+k]*w; a3 += hr[384+k]*w;
        }
        t[(rg*4+0)*64+j]=a0; t[(rg*4+1)*64+j]=a1; t[(rg*4+2)*64+j]=a2; t[(rg*4+3)*64+j]=a3;
    }
    __syncthreads();
    for (int idx = tid; idx < 16*64; idx += 256){
        int rg = idx >> 6, j = idx & 63;
        const float* ar = adj_s + rg*4*64;
        float bb = b2[j];
        float a0=bb,a1=bb,a2=bb,a3=bb;
        #pragma unroll 8
        for (int k = 0; k < 64; k++){
            float w = t[k*64+j];
            a0 += ar[k]*w; a1 += ar[64+k]*w; a2 += ar[128+k]*w; a3 += ar[192+k]*w;
        }
        h[(rg*4+0)*64+j]=fmaxf(a0,0.f); h[(rg*4+1)*64+j]=fmaxf(a1,0.f);
        h[(rg*4+2)*64+j]=fmaxf(a2,0.f); h[(rg*4+3)*64+j]=fmaxf(a3,0.f);
    }
    __syncthreads();
    for (int idx = tid; idx < 16*32; idx += 256){
        int rg = idx >> 5, j = idx & 31;
        const float* hr = h + rg*4*64;
        float a0=0.f,a1=0.f,a2=0.f,a3=0.f;
        #pragma unroll 8
        for (int k = 0; k < 64; k++){
            float w = W3[k*32+j];
            a0 += hr[k]*w; a1 += hr[64+k]*w; a2 += hr[128+k]*w; a3 += hr[192+k]*w;
        }
        t[(rg*4+0)*32+j]=a0; t[(rg*4+1)*32+j]=a1; t[(rg*4+2)*32+j]=a2; t[(rg*4+3)*32+j]=a3;
    }
    __syncthreads();
    float* outp = (branch == 0) ? (g_xenc + g*2048) : (g_denc + g*2048);
    for (int idx = tid; idx < 16*32; idx += 256){
        int rg = idx >> 5, j = idx & 31;
        const float* ar = adj_s + rg*4*64;
        float bb = b3[j];
        float a0=bb,a1=bb,a2=bb,a3=bb;
        #pragma unroll 8
        for (int k = 0; k < 64; k++){
            float w = t[k*32+j];
            a0 += ar[k]*w; a1 += ar[64+k]*w; a2 += ar[128+k]*w; a3 += ar[192+k]*w;
        }
        h[(rg*4+0)*32+j]=a0; h[(rg*4+1)*32+j]=a1; h[(rg*4+2)*32+j]=a2; h[(rg*4+3)*32+j]=a3;
        outp[(rg*4+0)*32+j]=a0; outp[(rg*4+1)*32+j]=a1; outp[(rg*4+2)*32+j]=a2; outp[(rg*4+3)*32+j]=a3;
    }
    __syncthreads();
    if (branch == 0 && tid < 64){
        float s = 0.f;
        #pragma unroll
        for (int f = 0; f < 32; f++){ float v = h[tid*32+f]; s += v*v; }
        g_x2[g*64 + tid] = s;
    }
}

// ---------------- prep: vwd precompute + attn/bernoulli (merged) ----------
__global__ void prep_kernel(const float* __restrict__ dp, const float* __restrict__ wl,
                            const float* __restrict__ fc1w, const float* __restrict__ fc2w,
                            const float* __restrict__ mlp_w, const float* __restrict__ mlp_b,
                            const float* __restrict__ mlp2_w, const float* __restrict__ mlp2_b)
{
    __shared__ float w3s[3*960];
    __shared__ float wls[960];
    __shared__ float yw[32][32];
    __shared__ float z[33];
    __shared__ float nrm[32];
    __shared__ float klsh[64];
    int tid = threadIdx.x;
    int d = blockIdx.x;

    for (int e = tid; e < 960; e += 256) wls[e] = wl[e];
    for (int e = tid; e < 2880; e += 256){
        int c = e / 960, j = e - c*960;
        float acc = 0.f;
        #pragma unroll 8
        for (int r = 0; r < 64; r++) acc += fc2w[c*64+r] * fc1w[r*960+j];
        w3s[e] = acc;
    }
    for (int e = tid; e < 1024; e += 256){
        int b = e >> 5, f = e & 31;
        float ss = 0.f, sw = 0.f;
        #pragma unroll 8
        for (int n = 0; n < 64; n++){
            float v = g_xenc[(b*64+n)*32 + f];
            ss += v*v;
            sw += mlp_w[n]*v;
        }
        yw[b][f] = sw / (sqrtf(ss) + 1e-12f);
    }
    const float* de = g_denc + d*2048;
    if (tid >= 64 && tid < 96){
        int f = tid - 64;
        float s = 0.f;
        #pragma unroll 8
        for (int m = 0; m < 64; m++){ float v = de[m*32+f]; s += v*v; }
        nrm[f] = sqrtf(s) + 1e-12f;
    }
    __syncthreads();
    {
        int base = d*32;
        for (int i = tid; i < 4096; i += 256){
            const float* dr = dp + (size_t)i*32;
            float s=0.f, t0=0.f, t1=0.f, t2=0.f;
            #pragma unroll 8
            for (int k = 0; k < 32; k++){
                float v = dr[k];
                s  += v * wls[base+k];
                t0 += v * w3s[base+k];
                t1 += v * w3s[960+base+k];
                t2 += v * w3s[1920+base+k];
            }
            g_vwd[d*4096 + i] = make_float4(s, t0, t1, t2);
        }
    }
    if (tid < 32){
        float acc = 0.f;
        #pragma unroll
        for (int b = 0; b < 32; b++) acc += mlp2_w[b]*yw[b][tid];
        z[tid] = acc;
    }
    if (tid == 32){
        float s = 0.f;
        #pragma unroll
        for (int b = 0; b < 32; b++) s += mlp2_w[b];
        z[32] = mlp_b[0]*s + mlp2_b[0];
    }
    __syncthreads();
    if (tid < 64){
        int m = tid;
        float p = z[32];
        #pragma unroll
        for (int f = 0; f < 32; f++) p += (de[m*32+f]/nrm[f]) * z[f];
        float attn = 1.f/(1.f + expf(-p));
        float u = jax_uniform_1920(d*64 + m);
        float bern = (u < attn) ? 1.f : 0.f;
        float ss = 0.f;
        #pragma unroll
        for (int f = 0; f < 32; f++){
            float v = de[m*32+f];
            g_dsamp[d*2048 + m*32+f] = bern*v;
            ss += v*v;
        }
        g_y2[d*64+m] = bern*ss;
        klsh[m] = attn*logf(attn*2.f) + (1.f-attn)*logf((1.f-attn)*2.f);
    }
    __syncthreads();
    if (tid == 0){
        float s = 0.f;
        for (int i = 0; i < 64; i++) s += klsh[i];
        g_klpart[d] = s;
    }
}

// ---------------- Sinkhorn: one WARP per lambda, zero block bars in loop --
// Block (d,b): 8 warps = 8 lambdas. Shared Ms (stride 65); per-warp Km tile.
// Lane l owns cols {l,l+32} and rows {l,l+32}; all smem reads conflict-free
// (col access lane-stride 1; row access lane-stride 65 == 1 mod 32).
// Smem layout (floats): Ms[0,4160), Km[4160, 4160+8*4160), ui[8*64], vi[8*64],
// rstat float2[8*64]. xs/ds staged in Km area during Ms build.
#define MSTR 65
#define MSZ  (64*MSTR)   // 4160
__global__ void __launch_bounds__(256)
sinkhorn_kernel(const int* __restrict__ num_node, const int* __restrict__ dict_nnode)
{
    extern __shared__ float S[];
    float*  Ms  = S;
    float*  Km  = S + MSZ;
    float*  uiA = S + MSZ*9;            // 9*4160 = 37440
    float*  viA = uiA + 512;
    float2* rst = (float2*)(viA + 512); // 8*64 float2

    int d = blockIdx.x, b = blockIdx.y;
    int tid = threadIdx.x, w = tid >> 5, lane = tid & 31;
    int nn = num_node[b], dn = dict_nnode[d];

    // stage xenc/dsamp into (unused yet) Km area
    float* xs = Km;
    float* ds = Km + 2048;
    {
        const float4* xg4 = (const float4*)(g_xenc + b*2048);
        const float4* dg4 = (const float4*)(g_dsamp + d*2048);
        float4* xs4 = (float4*)xs; float4* ds4 = (float4*)ds;
        for (int i = tid; i < 512; i += 256){ xs4[i] = xg4[i]; ds4[i] = dg4[i]; }
    }
    __syncthreads();
    for (int i = tid; i < 4096; i += 256){
        int n = i >> 6, m = i & 63;
        const float4* xr = (const float4*)(xs + n*32);
        const float4* dr = (const float4*)(ds + m*32);
        float acc = 0.f;
        #pragma unroll
        for (int j = 0; j < 8; j++){
            float4 a = xr[j], e = dr[j];
            acc += a.x*e.x + a.y*e.y + a.z*e.z + a.w*e.w;
        }
        Ms[n*MSTR+m] = g_x2[b*64+n] + g_y2[d*64+m] - 2.f*acc;
    }
    __syncthreads();

    // ---- per-warp lambda ----
    float lam = c_lamda[w];
    float* Kw  = Km  + w*MSZ;
    float* uiw = uiA + w*64;
    float* viw = viA + w*64;
    float2* rw = rst + w*64;

    // build Km_w = mask * exp(-Ms*lam)
    for (int i = lane; i < 4096; i += 32){
        int r = i >> 6, c = i & 63;
        float mv = Ms[r*MSTR+c];
        Kw[r*MSTR+c] = (r < nn && c < dn) ? __expf(-mv*lam) : 0.f;
    }
    uiw[lane] = 1.f; uiw[lane+32] = 1.f;
    __syncwarp();

    int c0 = lane, c1 = lane + 32;
    float wj0 = (c0 < dn) ? 1.f/(float)dn : 0.f;
    float wj1 = (c1 < dn) ? 1.f/(float)dn : 0.f;
    float wi0 = (c0 < nn) ? 1.f/(float)nn : 0.f;
    float wi1 = (c1 < nn) ? 1.f/(float)nn : 0.f;
    const float* kr0 = Kw + c0*MSTR;
    const float* kr1 = Kw + c1*MSTR;

    float u0 = 1.f, u1 = 1.f;
    for (int it = 0; it < 10; it++){
        // colsum for cols c0,c1
        float s0 = 0.f, s1 = 0.f;
        #pragma unroll 8
        for (int r = 0; r < 64; r++){
            float u = uiw[r];
            s0 += Kw[r*MSTR + c0] * u;
            s1 += Kw[r*MSTR + c1] * u;
        }
        viw[c0] = __fdividef(wj0, s0 + 1e-6f);
        viw[c1] = __fdividef(wj1, s1 + 1e-6f);
        __syncwarp();
        // rowsum for rows c0,c1
        s0 = 0.f; s1 = 0.f;
        #pragma unroll 8
        for (int c = 0; c < 64; c++){
            float v = viw[c];
            s0 += kr0[c] * v;
            s1 += kr1[c] * v;
        }
        u0 = __fdividef(wi0, s0 + 1e-6f);
        u1 = __fdividef(wi1, s1 + 1e-6f);
        uiw[c0] = u0;
        uiw[c1] = u1;
        __syncwarp();
    }

    // row stats for rows c0,c1 (conflict-free row reads)
    {
        float gmx0 = -3.4e38f, gmn0 = 3.4e38f, gmx1 = -3.4e38f, gmn1 = 3.4e38f;
        #pragma unroll 8
        for (int c = 0; c < 64; c++){
            float v = viw[c];
            float g0 = u0 * kr0[c] * v;
            float g1 = u1 * kr1[c] * v;
            gmx0 = fmaxf(gmx0, g0); gmn0 = fminf(gmn0, g0);
            gmx1 = fmaxf(gmx1, g1); gmn1 = fminf(gmn1, g1);
        }
        rw[c0] = make_float2(gmn0, __fdividef(1.f, gmx0 - gmn0 + 1e-6f));
        rw[c1] = make_float2(gmn1, __fdividef(1.f, gmx1 - gmn1 + 1e-6f));
    }
    __syncwarp();

    // projection epilogue, coalesced vwd reads: lane sweeps cols c0,c1 over all rows
    const float4* vw = g_vwd + d*4096;
    float v0 = viw[c0], v1 = viw[c1];
    float a0=0.f, a1=0.f, a2=0.f, a3=0.f;
    #pragma unroll 4
    for (int r = 0; r < 64; r++){
        float ur = uiw[r];
        float2 st = rw[r];
        float g, gm; float4 wv;
        g = ur * Kw[r*MSTR + c0] * v0;
        gm = (g - st.x) * st.y * Ms[r*MSTR + c0];
        wv = vw[r*64 + c0];
        a0 += gm*wv.x; a1 += gm*wv.y; a2 += gm*wv.z; a3 += gm*wv.w;
        g = ur * Kw[r*MSTR + c1] * v1;
        gm = (g - st.x) * st.y * Ms[r*MSTR + c1];
        wv = vw[r*64 + c1];
        a0 += gm*wv.x; a1 += gm*wv.y; a2 += gm*wv.z; a3 += gm*wv.w;
    }
    #pragma unroll
    for (int o = 16; o; o >>= 1){
        a0 += __shfl_xor_sync(0xffffffffu, a0, o);
        a1 += __shfl_xor_sync(0xffffffffu, a1, o);
        a2 += __shfl_xor_sync(0xffffffffu, a2, o);
        a3 += __shfl_xor_sync(0xffffffffu, a3, o);
    }
    if (lane == 0) g_part[(w*32+b)*30 + d] = make_float4(a0,a1,a2,a3);
}

// ---------------- final: softmax over l + folded head + KL ----------------
__global__ void final_kernel(const float* __restrict__ fc1b,
    const float* __restrict__ fc2w, const float* __restrict__ fc2b,
    float* __restrict__ out, int out_size)
{
    __shared__ float4 pl[8];
    int b = blockIdx.x, tid = threadIdx.x;
    int w = tid >> 5, lane = tid & 31;

    float4 a = make_float4(0.f,0.f,0.f,0.f);
    if (lane < 30) a = g_part[(w*32+b)*30 + lane];
    #pragma unroll
    for (int o = 16; o; o >>= 1){
        a.x += __shfl_xor_sync(0xffffffffu, a.x, o);
        a.y += __shfl_xor_sync(0xffffffffu, a.y, o);
        a.z += __shfl_xor_sync(0xffffffffu, a.z, o);
        a.w += __shfl_xor_sync(0xffffffffu, a.w, o);
    }
    if (lane == 0) pl[w] = a;
    __syncthreads();
    if (tid == 0){
        float mx = pl[0].x;
        #pragma unroll
        for (int l = 1; l < 8; l++) mx = fmaxf(mx, pl[l].x);
        float s = 0.f;
        float co[8];
        #pragma unroll
        for (int l = 0; l < 8; l++){ co[l] = expf(pl[l].x - mx); s += co[l]; }
        float t0=0.f, t1=0.f, t2=0.f;
        #pragma unroll
        for (int l = 0; l < 8; l++){
            float cf = co[l]/s;
            t0 += cf*pl[l].y; t1 += cf*pl[l].z; t2 += cf*pl[l].w;
        }
        float cc0=fc2b[0], cc1=fc2b[1], cc2=fc2b[2];
        for (int r = 0; r < 64; r++){
            float fb = fc1b[r];
            cc0 += fc2w[r]*fb; cc1 += fc2w[64+r]*fb; cc2 += fc2w[128+r]*fb;
        }
        out[b*3+0] = t0 + cc0;
        out[b*3+1] = t1 + cc1;
        out[b*3+2] = t2 + cc2;
    }
    if (b == 0 && tid == 32 && out_size > 96){
        float s = 0.f;
        for (int d = 0; d < 30; d++) s += g_klpart[d];
        out[96] = s;
    }
}

// ---------------- launch ---------------------------------------------------
extern "C" void kernel_launch(void* const* d_in, const int* in_sizes, int n_in,
                              void* d_out, int out_size)
{
    const float* x          = (const float*)d_in[0];
    const float* adj        = (const float*)d_in[1];
    const int*   num_node   = (const int*)  d_in[2];
    const float* dict_feat  = (const float*)d_in[3];
    const float* dict_adj   = (const float*)d_in[4];
    const int*   dict_nnode = (const int*)  d_in[5];
    const float* eW1 = (const float*)d_in[6];
    const float* eb1 = (const float*)d_in[7];
    const float* eW2 = (const float*)d_in[8];
    const float* eb2 = (const float*)d_in[9];
    const float* eW3 = (const float*)d_in[10];
    const float* eb3 = (const float*)d_in[11];
    const float* dW1 = (const float*)d_in[12];
    const float* db1 = (const float*)d_in[13];
    const float* dW2 = (const float*)d_in[14];
    const float* db2 = (const float*)d_in[15];
    const float* dW3 = (const float*)d_in[16];
    const float* db3 = (const float*)d_in[17];
    const float* mlp_w  = (const float*)d_in[18];
    const float* mlp_b  = (const float*)d_in[19];
    const float* mlp2_w = (const float*)d_in[20];
    const float* mlp2_b = (const float*)d_in[21];
    const float* dist_para    = (const float*)d_in[22];
    const float* weight_lamda = (const float*)d_in[23];
    const float* fc1_w = (const float*)d_in[24];
    const float* fc1_b = (const float*)d_in[25];
    const float* fc2_w = (const float*)d_in[26];
    const float* fc2_b = (const float*)d_in[27];

    const int gcn_smem = (4096 + 4096 + 8192 + 8192) * (int)sizeof(float);  // 96 KB
    // sinkhorn smem: Ms(4160) + 8*Km(4160) + ui(512) + vi(512) + rstat(1024) floats
    const int sink_smem = (MSZ*9 + 512 + 512 + 1024) * (int)sizeof(float);  // ~158 KB
    cudaFuncSetAttribute(gcn_kernel, cudaFuncAttributeMaxDynamicSharedMemorySize, gcn_smem);
    cudaFuncSetAttribute(sinkhorn_kernel, cudaFuncAttributeMaxDynamicSharedMemorySize, sink_smem);

    gcn_kernel<<<62, 256, gcn_smem>>>(x, adj, eW1, eb1, eW2, eb2, eW3, eb3,
                                      dict_feat, dict_adj, dW1, db1, dW2, db2, dW3, db3);
    prep_kernel<<<30, 256>>>(dist_para, weight_lamda, fc1_w, fc2_w,
                             mlp_w, mlp_b, mlp2_w, mlp2_b);
    sinkhorn_kernel<<<dim3(30, 32), 256, sink_smem>>>(num_node, dict_nnode);
    final_kernel<<<32, 256>>>(fc1_b, fc2_w, fc2_b, (float*)d_out, out_size);
}

// round 16
// speedup vs baseline: 1.4576x; 1.4576x over previous
#include <cuda_runtime.h>
#include <cuda_bf16.h>
#include <cstdint>
#include <math.h>

#define B_  32
#define N_  64
#define D_  30
#define ND_ 64
#define H3_ 32
#define L_  8

// ---------------- device scratch ----------------
__device__ float g_xenc[B_*N_*H3_];
__device__ float g_x2[B_*N_];
__device__ float g_denc[D_*ND_*H3_];
__device__ float g_dsamp[D_*ND_*H3_];
__device__ float g_y2[D_*ND_];
__device__ float g_klpart[D_];
__device__ float4 g_vwd[D_*N_*ND_];          // [d][i] -> (s, t0, t1, t2)  2 MB
__device__ float4 g_part[L_*B_*D_];          // per (l,b,d) partial (s,t0,t1,t2)

__constant__ float c_lamda[8] = {0.01f,0.1f,0.5f,1.0f,3.0f,5.0f,10.0f,20.0f};

// group barrier: 256 threads of lambda-group g (ids 1,2)
#define GBAR(g) asm volatile("bar.sync %0, %1;" :: "r"((g)+1), "r"(256) : "memory")

// ---------------- JAX threefry2x32 (partitionable) ------------------
__device__ __forceinline__ uint32_t rotl32(uint32_t x, int r){
    return (x << r) | (x >> (32 - r));
}
__device__ float jax_uniform_1920(int i){
    uint32_t x0 = 0u;
    uint32_t x1 = (uint32_t)i;
    const uint32_t k0 = 0u, k1 = 42u;
    const uint32_t k2 = 0u ^ 42u ^ 0x1BD11BDAu;
    x0 += k0; x1 += k1;
    #define FOUR_ROUNDS(a,b,c,d) \
        x0 += x1; x1 = rotl32(x1,a); x1 ^= x0; \
        x0 += x1; x1 = rotl32(x1,b); x1 ^= x0; \
        x0 += x1; x1 = rotl32(x1,c); x1 ^= x0; \
        x0 += x1; x1 = rotl32(x1,d); x1 ^= x0;
    FOUR_ROUNDS(13,15,26,6);  x0 += k1; x1 += k2 + 1u;
    FOUR_ROUNDS(17,29,16,24); x0 += k2; x1 += k0 + 2u;
    FOUR_ROUNDS(13,15,26,6);  x0 += k0; x1 += k1 + 3u;
    FOUR_ROUNDS(17,29,16,24); x0 += k1; x1 += k2 + 4u;
    FOUR_ROUNDS(13,15,26,6);  x0 += k2; x1 += k0 + 5u;
    #undef FOUR_ROUNDS
    uint32_t bits = x0 ^ x1;
    uint32_t fb = (bits >> 9) | 0x3f800000u;
    return __uint_as_float(fb) - 1.0f;
}

// ---------------- GCN (both branches, 512 threads for latency hiding) -----
__global__ void gcn_kernel(
    const float* __restrict__ xg0, const float* __restrict__ adjg0,
    const float* __restrict__ eW1, const float* __restrict__ eb1,
    const float* __restrict__ eW2, const float* __restrict__ eb2,
    const float* __restrict__ eW3, const float* __restrict__ eb3,
    const float* __restrict__ xg1, const float* __restrict__ adjg1,
    const float* __restrict__ dW1, const float* __restrict__ db1,
    const float* __restrict__ dW2, const float* __restrict__ db2,
    const float* __restrict__ dW3, const float* __restrict__ db3)
{
    extern __shared__ float sm[];
    float* adj_s = sm;             // 4096
    float* x_s   = sm + 4096;      // 4096
    float* t     = sm + 8192;      // 8192
    float* h     = sm + 16384;     // 8192
    int branch = (blockIdx.x >= 32) ? 1 : 0;
    int g = branch ? (blockIdx.x - 32) : blockIdx.x;
    const float* x   = (branch ? xg1   : xg0)   + g*64*64;
    const float* adj = (branch ? adjg1 : adjg0) + g*64*64;
    const float* W1 = branch ? dW1 : eW1; const float* b1 = branch ? db1 : eb1;
    const float* W2 = branch ? dW2 : eW2; const float* b2 = branch ? db2 : eb2;
    const float* W3 = branch ? dW3 : eW3; const float* b3 = branch ? db3 : eb3;
    int tid = threadIdx.x;

    for (int i = tid; i < 4096; i += 512){ adj_s[i] = adj[i]; x_s[i] = x[i]; }
    __syncthreads();

    for (int idx = tid; idx < 16*128; idx += 512){
        int rg = idx >> 7, j = idx & 127;
        const float* xr = x_s + rg*4*64;
        float a0=0.f,a1=0.f,a2=0.f,a3=0.f;
        #pragma unroll 8
        for (int k = 0; k < 64; k++){
            float w = W1[k*128+j];
            a0 += xr[k]*w; a1 += xr[64+k]*w; a2 += xr[128+k]*w; a3 += xr[192+k]*w;
        }
        t[(rg*4+0)*128+j]=a0; t[(rg*4+1)*128+j]=a1; t[(rg*4+2)*128+j]=a2; t[(rg*4+3)*128+j]=a3;
    }
    __syncthreads();
    for (int idx = tid; idx < 16*128; idx += 512){
        int rg = idx >> 7, j = idx & 127;
        const float* ar = adj_s + rg*4*64;
        float bb = b1[j];
        float a0=bb,a1=bb,a2=bb,a3=bb;
        #pragma unroll 8
        for (int k = 0; k < 64; k++){
            float w = t[k*128+j];
            a0 += ar[k]*w; a1 += ar[64+k]*w; a2 += ar[128+k]*w; a3 += ar[192+k]*w;
        }
        h[(rg*4+0)*128+j]=fmaxf(a0,0.f); h[(rg*4+1)*128+j]=fmaxf(a1,0.f);
        h[(rg*4+2)*128+j]=fmaxf(a2,0.f); h[(rg*4+3)*128+j]=fmaxf(a3,0.f);
    }
    __syncthreads();
    for (int idx = tid; idx < 16*64; idx += 512){
        int rg = idx >> 6, j = idx & 63;
        const float* hr = h + rg*4*128;
        float a0=0.f,a1=0.f,a2=0.f,a3=0.f;
        #pragma unroll 8
        for (int k = 0; k < 128; k++){
            float w = W2[k*64+j];
            a0 += hr[k]*w; a1 += hr[128+k]*w; a2 += hr[256+k]*w; a3 += hr[384+k]*w;
        }
        t[(rg*4+0)*64+j]=a0; t[(rg*4+1)*64+j]=a1; t[(rg*4+2)*64+j]=a2; t[(rg*4+3)*64+j]=a3;
    }
    __syncthreads();
    for (int idx = tid; idx < 16*64; idx += 512){
        int rg = idx >> 6, j = idx & 63;
        const float* ar = adj_s + rg*4*64;
        float bb = b2[j];
        float a0=bb,a1=bb,a2=bb,a3=bb;
        #pragma unroll 8
        for (int k = 0; k < 64; k++){
            float w = t[k*64+j];
            a0 += ar[k]*w; a1 += ar[64+k]*w; a2 += ar[128+k]*w; a3 += ar[192+k]*w;
        }
        h[(rg*4+0)*64+j]=fmaxf(a0,0.f); h[(rg*4+1)*64+j]=fmaxf(a1,0.f);
        h[(rg*4+2)*64+j]=fmaxf(a2,0.f); h[(rg*4+3)*64+j]=fmaxf(a3,0.f);
    }
    __syncthreads();
    for (int idx = tid; idx < 16*32; idx += 512){
        int rg = idx >> 5, j = idx & 31;
        const float* hr = h + rg*4*64;
        float a0=0.f,a1=0.f,a2=0.f,a3=0.f;
        #pragma unroll 8
        for (int k = 0; k < 64; k++){
            float w = W3[k*32+j];
            a0 += hr[k]*w; a1 += hr[64+k]*w; a2 += hr[128+k]*w; a3 += hr[192+k]*w;
        }
        t[(rg*4+0)*32+j]=a0; t[(rg*4+1)*32+j]=a1; t[(rg*4+2)*32+j]=a2; t[(rg*4+3)*32+j]=a3;
    }
    __syncthreads();
    float* outp = (branch == 0) ? (g_xenc + g*2048) : (g_denc + g*2048);
    for (int idx = tid; idx < 16*32; idx += 512){
        int rg = idx >> 5, j = idx & 31;
        const float* ar = adj_s + rg*4*64;
        float bb = b3[j];
        float a0=bb,a1=bb,a2=bb,a3=bb;
        #pragma unroll 8
        for (int k = 0; k < 64; k++){
            float w = t[k*32+j];
            a0 += ar[k]*w; a1 += ar[64+k]*w; a2 += ar[128+k]*w; a3 += ar[192+k]*w;
        }
        h[(rg*4+0)*32+j]=a0; h[(rg*4+1)*32+j]=a1; h[(rg*4+2)*32+j]=a2; h[(rg*4+3)*32+j]=a3;
        outp[(rg*4+0)*32+j]=a0; outp[(rg*4+1)*32+j]=a1; outp[(rg*4+2)*32+j]=a2; outp[(rg*4+3)*32+j]=a3;
    }
    __syncthreads();
    if (branch == 0 && tid < 64){
        float s = 0.f;
        #pragma unroll
        for (int f = 0; f < 32; f++){ float v = h[tid*32+f]; s += v*v; }
        g_x2[g*64 + tid] = s;
    }
}

// ---------------- prep: vwd precompute + attn/bernoulli (512 threads) -----
__global__ void prep_kernel(const float* __restrict__ dp, const float* __restrict__ wl,
                            const float* __restrict__ fc1w, const float* __restrict__ fc2w,
                            const float* __restrict__ mlp_w, const float* __restrict__ mlp_b,
                            const float* __restrict__ mlp2_w, const float* __restrict__ mlp2_b)
{
    __shared__ float w3s[3*960];
    __shared__ float wls[960];
    __shared__ float yw[32][32];
    __shared__ float z[33];
    __shared__ float nrm[32];
    __shared__ float klsh[64];
    int tid = threadIdx.x;
    int d = blockIdx.x;

    for (int e = tid; e < 960; e += 512) wls[e] = wl[e];
    for (int e = tid; e < 2880; e += 512){
        int c = e / 960, j = e - c*960;
        float acc = 0.f;
        #pragma unroll 8
        for (int r = 0; r < 64; r++) acc += fc2w[c*64+r] * fc1w[r*960+j];
        w3s[e] = acc;
    }
    for (int e = tid; e < 1024; e += 512){
        int b = e >> 5, f = e & 31;
        float ss = 0.f, sw = 0.f;
        #pragma unroll 8
        for (int n = 0; n < 64; n++){
            float v = g_xenc[(b*64+n)*32 + f];
            ss += v*v;
            sw += mlp_w[n]*v;
        }
        yw[b][f] = sw / (sqrtf(ss) + 1e-12f);
    }
    const float* de = g_denc + d*2048;
    if (tid >= 64 && tid < 96){
        int f = tid - 64;
        float s = 0.f;
        #pragma unroll 8
        for (int m = 0; m < 64; m++){ float v = de[m*32+f]; s += v*v; }
        nrm[f] = sqrtf(s) + 1e-12f;
    }
    __syncthreads();
    {
        int base = d*32;
        for (int i = tid; i < 4096; i += 512){
            const float* dr = dp + (size_t)i*32;
            float s=0.f, t0=0.f, t1=0.f, t2=0.f;
            #pragma unroll 8
            for (int k = 0; k < 32; k++){
                float v = dr[k];
                s  += v * wls[base+k];
                t0 += v * w3s[base+k];
                t1 += v * w3s[960+base+k];
                t2 += v * w3s[1920+base+k];
            }
            g_vwd[d*4096 + i] = make_float4(s, t0, t1, t2);
        }
    }
    if (tid < 32){
        float acc = 0.f;
        #pragma unroll
        for (int b = 0; b < 32; b++) acc += mlp2_w[b]*yw[b][tid];
        z[tid] = acc;
    }
    if (tid == 32){
        float s = 0.f;
        #pragma unroll
        for (int b = 0; b < 32; b++) s += mlp2_w[b];
        z[32] = mlp_b[0]*s + mlp2_b[0];
    }
    __syncthreads();
    if (tid < 64){
        int m = tid;
        float p = z[32];
        #pragma unroll
        for (int f = 0; f < 32; f++) p += (de[m*32+f]/nrm[f]) * z[f];
        float attn = 1.f/(1.f + expf(-p));
        float u = jax_uniform_1920(d*64 + m);
        float bern = (u < attn) ? 1.f : 0.f;
        float ss = 0.f;
        #pragma unroll
        for (int f = 0; f < 32; f++){
            float v = de[m*32+f];
            g_dsamp[d*2048 + m*32+f] = bern*v;
            ss += v*v;
        }
        g_y2[d*64+m] = bern*ss;
        klsh[m] = attn*logf(attn*2.f) + (1.f-attn)*logf((1.f-attn)*2.f);
    }
    __syncthreads();
    if (tid == 0){
        float s = 0.f;
        for (int i = 0; i < 64; i++) s += klsh[i];
        g_klpart[d] = s;
    }
}

// ---------------- Sinkhorn: 512 thr = 2 lambda-groups x 256 (R12 proven) --
__global__ void __launch_bounds__(512, 2)
sinkhorn_kernel(const int* __restrict__ num_node, const int* __restrict__ dict_nnode)
{
    __shared__ __align__(16) float Ms[64*68];
    __shared__ __align__(16) float xs[2048];
    __shared__ __align__(16) float ds[2048];
    __shared__ __align__(16) float ui[2][64];
    __shared__ __align__(16) float vi[2][64];
    __shared__ float wis[64], wjs[64];
    __shared__ float red[2][4][64];
    __shared__ float red2[2][4][64];
    __shared__ float4 wred[2][8];

    int d = blockIdx.x, b = blockIdx.y;
    int tid = threadIdx.x;
    int g  = tid >> 8;          // lambda group 0/1
    int gt = tid & 255;
    int c = gt & 63, q = gt >> 6;
    int lw = (tid >> 5) & 7;    // warp index within group
    int nn = num_node[b], dn = dict_nnode[d];

    if (tid < 64){
        wis[tid] = (tid < nn) ? 1.f/(float)nn : 0.f;
        wjs[tid] = (tid < dn) ? 1.f/(float)dn : 0.f;
    }
    {
        const float4* xg4 = (const float4*)(g_xenc + b*2048);
        const float4* dg4 = (const float4*)(g_dsamp + d*2048);
        float4* xs4 = (float4*)xs; float4* ds4 = (float4*)ds;
        for (int i = tid; i < 512; i += 512){ xs4[i] = xg4[i]; ds4[i] = dg4[i]; }
    }
    __syncthreads();
    for (int i = tid; i < 4096; i += 512){
        int n = i >> 6, m = i & 63;
        const float4* xr = (const float4*)(xs + n*32);
        const float4* dr = (const float4*)(ds + m*32);
        float acc = 0.f;
        #pragma unroll
        for (int j = 0; j < 8; j++){
            float4 a = xr[j], e = dr[j];
            acc += a.x*e.x + a.y*e.y + a.z*e.z + a.w*e.w;
        }
        Ms[n*68+m] = g_x2[b*64+n] + g_y2[d*64+m] - 2.f*acc;
    }
    __syncthreads();

    const float4* vw = g_vwd + d*4096;
    bool cInDn = (c < dn), cInNn = (c < nn);
    int base = q*16;

    for (int pass = 0; pass < 4; pass++){
        int l = g*4 + pass;
        float lam = c_lamda[l];
        float regA[16], regB[16];
        #pragma unroll
        for (int n = 0; n < 16; n++){
            int row = base + n;
            regA[n] = (row < nn && cInDn) ? __expf(-Ms[row*68 + c]*lam) : 0.f;
        }
        #pragma unroll
        for (int mm = 0; mm < 16; mm++){
            int col = base + mm;
            regB[mm] = (cInNn && col < dn) ? __expf(-Ms[c*68 + col]*lam) : 0.f;
        }
        if (gt < 64) ui[g][gt] = 1.f;
        GBAR(g);

        for (int it = 0; it < 10; it++){
            float p = 0.f;
            const float4* u4p = (const float4*)(ui[g] + base);
            #pragma unroll
            for (int n = 0; n < 16; n += 4){
                float4 u4 = u4p[n >> 2];
                p += regA[n]*u4.x + regA[n+1]*u4.y + regA[n+2]*u4.z + regA[n+3]*u4.w;
            }
            red[g][q][c] = p;
            GBAR(g);
            if (gt < 64)
                vi[g][gt] = __fdividef(wjs[gt],
                    red[g][0][gt]+red[g][1][gt]+red[g][2][gt]+red[g][3][gt] + 1e-6f);
            GBAR(g);
            p = 0.f;
            const float4* v4p = (const float4*)(vi[g] + base);
            #pragma unroll
            for (int mm = 0; mm < 16; mm += 4){
                float4 v4 = v4p[mm >> 2];
                p += regB[mm]*v4.x + regB[mm+1]*v4.y + regB[mm+2]*v4.z + regB[mm+3]*v4.w;
            }
            red[g][q][c] = p;
            GBAR(g);
            if (gt < 64)
                ui[g][gt] = __fdividef(wis[gt],
                    red[g][0][gt]+red[g][1][gt]+red[g][2][gt]+red[g][3][gt] + 1e-6f);
            GBAR(g);
        }

        // row min/max of G[c][:]  (partials in red/red2, combined redundantly)
        float uic = ui[g][c];
        float gmx = -3.4e38f, gmn = 3.4e38f;
        {
            const float4* v4p = (const float4*)(vi[g] + base);
            #pragma unroll
            for (int mm = 0; mm < 16; mm += 4){
                float4 v4 = v4p[mm >> 2];
                float g0 = uic*regB[mm]*v4.x,   g1 = uic*regB[mm+1]*v4.y;
                float g2 = uic*regB[mm+2]*v4.z, g3 = uic*regB[mm+3]*v4.w;
                gmx = fmaxf(gmx, fmaxf(fmaxf(g0,g1), fmaxf(g2,g3)));
                gmn = fminf(gmn, fminf(fminf(g0,g1), fminf(g2,g3)));
            }
        }
        red[g][q][c] = gmx; red2[g][q][c] = gmn;
        GBAR(g);
        float rmx = fmaxf(fmaxf(red[g][0][c],red[g][1][c]), fmaxf(red[g][2][c],red[g][3][c]));
        float rmn = fminf(fminf(red2[g][0][c],red2[g][1][c]), fminf(red2[g][2][c],red2[g][3][c]));
        float rinv = __fdividef(1.f, rmx - rmn + 1e-6f);

        // fused projection epilogue
        float a0=0.f, a1=0.f, a2=0.f, a3=0.f;
        {
            const float4* v4p = (const float4*)(vi[g] + base);
            const float4* m4p = (const float4*)(Ms + c*68 + base);
            #pragma unroll
            for (int mm = 0; mm < 16; mm += 4){
                float4 v4 = v4p[mm >> 2];
                float4 m4 = m4p[mm >> 2];
                float gg, gm; float4 w;
                gg = uic*regB[mm+0]*v4.x; gm = (gg - rmn)*rinv*m4.x; w = vw[c*64 + base + mm + 0];
                a0 += gm*w.x; a1 += gm*w.y; a2 += gm*w.z; a3 += gm*w.w;
                gg = uic*regB[mm+1]*v4.y; gm = (gg - rmn)*rinv*m4.y; w = vw[c*64 + base + mm + 1];
                a0 += gm*w.x; a1 += gm*w.y; a2 += gm*w.z; a3 += gm*w.w;
                gg = uic*regB[mm+2]*v4.z; gm = (gg - rmn)*rinv*m4.z; w = vw[c*64 + base + mm + 2];
                a0 += gm*w.x; a1 += gm*w.y; a2 += gm*w.z; a3 += gm*w.w;
                gg = uic*regB[mm+3]*v4.w; gm = (gg - rmn)*rinv*m4.w; w = vw[c*64 + base + mm + 3];
                a0 += gm*w.x; a1 += gm*w.y; a2 += gm*w.z; a3 += gm*w.w;
            }
        }
        #pragma unroll
        for (int o = 16; o; o >>= 1){
            a0 += __shfl_xor_sync(0xffffffffu, a0, o);
            a1 += __shfl_xor_sync(0xffffffffu, a1, o);
            a2 += __shfl_xor_sync(0xffffffffu, a2, o);
            a3 += __shfl_xor_sync(0xffffffffu, a3, o);
        }
        if ((tid & 31) == 0) wred[g][lw] = make_float4(a0,a1,a2,a3);
        GBAR(g);
        if (gt == 0){
            float4 s = wred[g][0];
            #pragma unroll
            for (int w = 1; w < 8; w++){
                float4 t = wred[g][w];
                s.x += t.x; s.y += t.y; s.z += t.z; s.w += t.w;
            }
            g_part[(l*32+b)*30 + d] = s;
        }
    }
}

// ---------------- final: softmax over l + folded head + KL ----------------
__global__ void final_kernel(const float* __restrict__ fc1b,
    const float* __restrict__ fc2w, const float* __restrict__ fc2b,
    float* __restrict__ out, int out_size)
{
    __shared__ float4 pl[8];
    int b = blockIdx.x, tid = threadIdx.x;
    int w = tid >> 5, lane = tid & 31;

    float4 a = make_float4(0.f,0.f,0.f,0.f);
    if (lane < 30) a = g_part[(w*32+b)*30 + lane];
    #pragma unroll
    for (int o = 16; o; o >>= 1){
        a.x += __shfl_xor_sync(0xffffffffu, a.x, o);
        a.y += __shfl_xor_sync(0xffffffffu, a.y, o);
        a.z += __shfl_xor_sync(0xffffffffu, a.z, o);
        a.w += __shfl_xor_sync(0xffffffffu, a.w, o);
    }
    if (lane == 0) pl[w] = a;
    __syncthreads();
    if (tid == 0){
        float mx = pl[0].x;
        #pragma unroll
        for (int l = 1; l < 8; l++) mx = fmaxf(mx, pl[l].x);
        float s = 0.f;
        float co[8];
        #pragma unroll
        for (int l = 0; l < 8; l++){ co[l] = expf(pl[l].x - mx); s += co[l]; }
        float t0=0.f, t1=0.f, t2=0.f;
        #pragma unroll
        for (int l = 0; l < 8; l++){
            float cf = co[l]/s;
            t0 += cf*pl[l].y; t1 += cf*pl[l].z; t2 += cf*pl[l].w;
        }
        float cc0=fc2b[0], cc1=fc2b[1], cc2=fc2b[2];
        for (int r = 0; r < 64; r++){
            float fb = fc1b[r];
            cc0 += fc2w[r]*fb; cc1 += fc2w[64+r]*fb; cc2 += fc2w[128+r]*fb;
        }
        out[b*3+0] = t0 + cc0;
        out[b*3+1] = t1 + cc1;
        out[b*3+2] = t2 + cc2;
    }
    if (b == 0 && tid == 32 && out_size > 96){
        float s = 0.f;
        for (int d = 0; d < 30; d++) s += g_klpart[d];
        out[96] = s;
    }
}

// ---------------- launch ---------------------------------------------------
extern "C" void kernel_launch(void* const* d_in, const int* in_sizes, int n_in,
                              void* d_out, int out_size)
{
    const float* x          = (const float*)d_in[0];
    const float* adj        = (const float*)d_in[1];
    const int*   num_node   = (const int*)  d_in[2];
    const float* dict_feat  = (const float*)d_in[3];
    const float* dict_adj   = (const float*)d_in[4];
    const int*   dict_nnode = (const int*)  d_in[5];
    const float* eW1 = (const float*)d_in[6];
    const float* eb1 = (const float*)d_in[7];
    const float* eW2 = (const float*)d_in[8];
    const float* eb2 = (const float*)d_in[9];
    const float* eW3 = (const float*)d_in[10];
    const float* eb3 = (const float*)d_in[11];
    const float* dW1 = (const float*)d_in[12];
    const float* db1 = (const float*)d_in[13];
    const float* dW2 = (const float*)d_in[14];
    const float* db2 = (const float*)d_in[15];
    const float* dW3 = (const float*)d_in[16];
    const float* db3 = (const float*)d_in[17];
    const float* mlp_w  = (const float*)d_in[18];
    const float* mlp_b  = (const float*)d_in[19];
    const float* mlp2_w = (const float*)d_in[20];
    const float* mlp2_b = (const float*)d_in[21];
    const float* dist_para    = (const float*)d_in[22];
    const float* weight_lamda = (const float*)d_in[23];
    const float* fc1_w = (const float*)d_in[24];
    const float* fc1_b = (const float*)d_in[25];
    const float* fc2_w = (const float*)d_in[26];
    const float* fc2_b = (const float*)d_in[27];

    const int gcn_smem = (4096 + 4096 + 8192 + 8192) * (int)sizeof(float);  // 96 KB
    cudaFuncSetAttribute(gcn_kernel, cudaFuncAttributeMaxDynamicSharedMemorySize, gcn_smem);

    gcn_kernel<<<62, 512, gcn_smem>>>(x, adj, eW1, eb1, eW2, eb2, eW3, eb3,
                                      dict_feat, dict_adj, dW1, db1, dW2, db2, dW3, db3);
    prep_kernel<<<30, 512>>>(dist_para, weight_lamda, fc1_w, fc2_w,
                             mlp_w, mlp_b, mlp2_w, mlp2_b);
    sinkhorn_kernel<<<dim3(30, 32), 512>>>(num_node, dict_nnode);
    final_kernel<<<32, 256>>>(fc1_b, fc2_w, fc2_b, (float*)d_out, out_size);
}